// round 11
// baseline (speedup 1.0000x reference)
#include <cuda_runtime.h>
#include <cuda_bf16.h>
#include <cstdint>
#include <cstddef>

// Problem dims
#define B_  32
#define NN_ 16
#define T_  256
#define D_  512
#define C_  512
#define M_  (B_ * T_)      // 8192 rows of v_mean

#define KT16 (D_ / 16)     // 32 k-tiles

// ---------------- scratch: operands pre-packed in HMMA fragment layout -----
// A frag (m16n8k16, row-major A): tile (mt, kt), lane 0..31 holds 8 bf16
//   (regs a0..a3 pairs) contiguously -> one LDG.128 per lane per tile.
//   index = (((mt*32 + kt)*32 + lane)*8 + idx)
// B frag (col-major B = t_feat[k][n] view): tile (nt, kt), lane holds 4 bf16
//   (regs b0,b1 pairs) -> one LDG.64.
//   index = (((nt*32 + kt)*32 + lane)*4 + idx)
static __device__ __align__(16) __nv_bfloat16 g_afh[(size_t)M_ * D_];
static __device__ __align__(16) __nv_bfloat16 g_afl[(size_t)M_ * D_];
static __device__ __align__(16) __nv_bfloat16 g_bfh[(size_t)C_ * D_];
static __device__ __align__(16) __nv_bfloat16 g_bfl[(size_t)C_ * D_];

// ---------------- helpers --------------------------------------------------
__device__ __forceinline__ bool is_split1(const int* sp) {
    int v = *sp;
    return (v == 1) || (v == 0x3F800000);
}

__device__ __forceinline__ void split_bf16(float a, __nv_bfloat16& hi, __nv_bfloat16& lo) {
    hi = __float2bfloat16(a);
    lo = __float2bfloat16(a - __bfloat162float(hi));
}

#define MMA16816(C, A, B)                                                    \
    asm volatile(                                                            \
        "mma.sync.aligned.m16n8k16.row.col.f32.bf16.bf16.f32 "               \
        "{%0,%1,%2,%3}, {%4,%5,%6,%7}, {%8,%9}, {%0,%1,%2,%3};"              \
        : "+f"((C)[0]), "+f"((C)[1]), "+f"((C)[2]), "+f"((C)[3])             \
        : "r"((A).x), "r"((A).y), "r"((A).z), "r"((A).w),                    \
          "r"((B).x), "r"((B).y))

// ---------------- kernel 1: normalize t_feat -> B fragments ----------------
__global__ __launch_bounds__(128)
void tnorm_kernel(const float* __restrict__ t, const int* __restrict__ split) {
    __shared__ float red[4];
    int c = blockIdx.x;
    const float4* tp = reinterpret_cast<const float4*>(t) + (size_t)c * (D_ / 4);
    float4 x = tp[threadIdx.x];
    float ss = x.x * x.x + x.y * x.y + x.z * x.z + x.w * x.w;
    #pragma unroll
    for (int off = 16; off > 0; off >>= 1)
        ss += __shfl_xor_sync(0xFFFFFFFFu, ss, off);
    int warp = threadIdx.x >> 5;
    if ((threadIdx.x & 31) == 0) red[warp] = ss;
    __syncthreads();
    ss = red[0] + red[1] + red[2] + red[3];

    float s = 1.0f;
    if (is_split1(split)) s = 1.0f / fmaxf(sqrtf(ss), 1e-12f);

    int d0 = threadIdx.x * 4;
    float v[4] = { x.x * s, x.y * s, x.z * s, x.w * s };
    int g = c & 7;
    size_t ntbase = ((size_t)(c >> 3) * KT16) * 32;   // nt*32 tiles, *32 lanes
    #pragma unroll
    for (int j = 0; j < 4; j++) {
        int d = d0 + j;
        int kk = d & 15;
        int lane = (g << 2) | ((kk & 7) >> 1);
        int idx  = (kk & 1) | ((kk >> 3) << 1);
        size_t off = ((ntbase + (size_t)(d >> 4) * 32 + lane) << 2) + idx;
        __nv_bfloat16 hi, lo;
        split_bf16(v[j], hi, lo);
        g_bfh[off] = hi;
        g_bfl[off] = lo;
    }
}

// ---------------- kernel 2: normalize-each-n + mean -> A fragments ---------
// One block per (b,t) row; 16 warps each normalize one n-row (warp-shuffle
// sumsq), reduce over n in smem, emit hi/lo bf16 into fragment layout.
__global__ __launch_bounds__(512)
void vmean_kernel(const float* __restrict__ v, const int* __restrict__ split) {
    __shared__ float sm[NN_ * D_];   // 32 KB
    int row  = blockIdx.x;           // b*256 + t
    int w    = threadIdx.x >> 5;     // n index
    int lane = threadIdx.x & 31;
    int bb = row >> 8;
    int tt = row & 255;

    const float4* vp = reinterpret_cast<const float4*>(v) +
                       ((size_t)((bb * NN_ + w) * T_ + tt)) * (D_ / 4);
    float4 x0 = vp[lane];
    float4 x1 = vp[lane + 32];
    float4 x2 = vp[lane + 64];
    float4 x3 = vp[lane + 96];

    float ss = x0.x * x0.x + x0.y * x0.y + x0.z * x0.z + x0.w * x0.w
             + x1.x * x1.x + x1.y * x1.y + x1.z * x1.z + x1.w * x1.w
             + x2.x * x2.x + x2.y * x2.y + x2.z * x2.z + x2.w * x2.w
             + x3.x * x3.x + x3.y * x3.y + x3.z * x3.z + x3.w * x3.w;
    #pragma unroll
    for (int off = 16; off > 0; off >>= 1)
        ss += __shfl_xor_sync(0xFFFFFFFFu, ss, off);

    float s = 1.0f;
    if (is_split1(split)) s = 1.0f / fmaxf(sqrtf(ss), 1e-12f);

    float4* smp = reinterpret_cast<float4*>(sm + w * D_);
    smp[lane]      = make_float4(x0.x * s, x0.y * s, x0.z * s, x0.w * s);
    smp[lane + 32] = make_float4(x1.x * s, x1.y * s, x1.z * s, x1.w * s);
    smp[lane + 64] = make_float4(x2.x * s, x2.y * s, x2.z * s, x2.w * s);
    smp[lane + 96] = make_float4(x3.x * s, x3.y * s, x3.z * s, x3.w * s);
    __syncthreads();

    int d = threadIdx.x;             // 0..511
    float acc = 0.0f;
    #pragma unroll
    for (int n = 0; n < NN_; n++) acc += sm[n * D_ + d];
    float a = acc * (1.0f / 16.0f);

    // fragment-layout store
    int r = row & 15, cc = d & 15;
    int fl  = ((r & 7) << 2) | ((cc & 7) >> 1);
    int idx = (cc & 1) | ((r >> 3) << 1) | ((cc >> 3) << 2);
    size_t off = ((((size_t)(row >> 4) * KT16 + (d >> 4)) * 32 + fl) << 3) + idx;
    __nv_bfloat16 hi, lo;
    split_bf16(a, hi, lo);
    g_afh[off] = hi;
    g_afl[off] = lo;
}

// ---------------- kernel 3: bf16-split mma.sync GEMM -----------------------
// D[m, c] = sum_d A[m,d]*B[c,d]; out[b][c][t] = D/tau, m = b*256+t.
// CTA tile 128x128 (16 warps, warp tile 32x32: 2 m-tiles x 4 n-tiles).
// 3 HMMAs per (tile, k16): hi*hi + hi*lo + lo*hi. Fragments LDG'd directly
// from the pre-packed arrays (L2-resident); register ping-pong buffering.
__global__ __launch_bounds__(512)
void gemm_mma_kernel(float* __restrict__ out) {
    int tid = threadIdx.x;
    int w = tid >> 5, lane = tid & 31;
    int wm = w >> 2, wn = w & 3;
    int m0 = blockIdx.y * 128 + wm * 32;
    int n0 = blockIdx.x * 128 + wn * 32;

    // per-lane fragment pointers (uint4 = one A frag, uint2 = one B frag)
    const uint4* pAh = reinterpret_cast<const uint4*>(g_afh) + (size_t)(m0 >> 4) * (KT16 * 32) + lane;
    const uint4* pAl = reinterpret_cast<const uint4*>(g_afl) + (size_t)(m0 >> 4) * (KT16 * 32) + lane;
    const uint2* pBh = reinterpret_cast<const uint2*>(g_bfh) + (size_t)(n0 >> 3) * (KT16 * 32) + lane;
    const uint2* pBl = reinterpret_cast<const uint2*>(g_bfl) + (size_t)(n0 >> 3) * (KT16 * 32) + lane;

    float acc[2][4][4];
    #pragma unroll
    for (int mi = 0; mi < 2; mi++)
        #pragma unroll
        for (int ni = 0; ni < 4; ni++)
            #pragma unroll
            for (int j = 0; j < 4; j++) acc[mi][ni][j] = 0.0f;

    uint4 Ah[2][2], Al[2][2];
    uint2 Bh[2][4], Bl[2][4];

    // preload k-tile 0 into buffer 0 (mtile stride = KT16*32 frags = 1024)
    #pragma unroll
    for (int mi = 0; mi < 2; mi++) {
        Ah[0][mi] = pAh[mi * (KT16 * 32)];
        Al[0][mi] = pAl[mi * (KT16 * 32)];
    }
    #pragma unroll
    for (int ni = 0; ni < 4; ni++) {
        Bh[0][ni] = pBh[ni * (KT16 * 32)];
        Bl[0][ni] = pBl[ni * (KT16 * 32)];
    }

    #pragma unroll
    for (int kt = 0; kt < KT16; kt++) {
        int cur = kt & 1, nxt = cur ^ 1;
        if (kt + 1 < KT16) {
            int ko = (kt + 1) * 32;
            #pragma unroll
            for (int mi = 0; mi < 2; mi++) {
                Ah[nxt][mi] = pAh[mi * (KT16 * 32) + ko];
                Al[nxt][mi] = pAl[mi * (KT16 * 32) + ko];
            }
            #pragma unroll
            for (int ni = 0; ni < 4; ni++) {
                Bh[nxt][ni] = pBh[ni * (KT16 * 32) + ko];
                Bl[nxt][ni] = pBl[ni * (KT16 * 32) + ko];
            }
        }
        #pragma unroll
        for (int mi = 0; mi < 2; mi++)
            #pragma unroll
            for (int ni = 0; ni < 4; ni++) {
                MMA16816(acc[mi][ni], Ah[cur][mi], Bh[cur][ni]);
                MMA16816(acc[mi][ni], Ah[cur][mi], Bl[cur][ni]);
                MMA16816(acc[mi][ni], Al[cur][mi], Bh[cur][ni]);
            }
    }

    // epilogue: out[b][c][t] (t contiguous, stride 256 per c)
    int b  = m0 >> 8;                      // CTA m-tile never crosses a b boundary
    int t  = (m0 & 255) + (lane >> 2);
    const float s = 1.0f / 0.07f;          // 1/tau (both splits)
    #pragma unroll
    for (int mi = 0; mi < 2; mi++) {
        #pragma unroll
        for (int ni = 0; ni < 4; ni++) {
            int c = n0 + ni * 8 + (lane & 3) * 2;
            float* p = out + (((size_t)b * C_ + c) << 8) + t + mi * 16;
            p[0]   = acc[mi][ni][0] * s;   // (t,   c)
            p[256] = acc[mi][ni][1] * s;   // (t,   c+1)
            p[8]   = acc[mi][ni][2] * s;   // (t+8, c)
            p[264] = acc[mi][ni][3] * s;   // (t+8, c+1)
        }
    }
}

// ---------------- launch ---------------------------------------------------
extern "C" void kernel_launch(void* const* d_in, const int* in_sizes, int n_in,
                              void* d_out, int out_size) {
    const float* v = nullptr;
    const float* t = nullptr;
    const int* split = nullptr;
    for (int i = 0; i < n_in; i++) {
        if (in_sizes[i] == B_ * NN_ * T_ * D_) v = (const float*)d_in[i];
        else if (in_sizes[i] == C_ * D_)       t = (const float*)d_in[i];
        else                                    split = (const int*)d_in[i];
    }
    float* out = (float*)d_out;

    tnorm_kernel<<<C_, 128>>>(t, split);
    vmean_kernel<<<M_, 512>>>(v, split);
    dim3 grid(C_ / 128, M_ / 128);   // (4, 64) = 256 CTAs
    gemm_mma_kernel<<<grid, 512>>>(out);
}

// round 16
// speedup vs baseline: 1.2083x; 1.2083x over previous
#include <cuda_runtime.h>
#include <cuda_fp16.h>
#include <cstdint>
#include <cstddef>

// Problem dims
#define B_  32
#define NN_ 16
#define T_  256
#define D_  512
#define C_  512
#define M_  (B_ * T_)      // 8192 rows of v_mean

#define KT16 (D_ / 16)     // 32 k-tiles

// ---------------- scratch: operands pre-packed in HMMA fragment layout -----
// A (fp16 hi only), m16n8k16 row-major A frag: tile (mt, kt), lane holds 8
//   fp16 = one uint4. index = ((mt*32 + kt)*32 + lane)  [uint4 units]
// B (fp16 hi + lo), col-major B frag: tile (nt, kt), lane holds 4 fp16 =
//   one uint2. index = ((nt*32 + kt)*32 + lane)  [uint2 units]
static __device__ __align__(16) __half g_afh[(size_t)M_ * D_];
static __device__ __align__(16) __half g_bfh[(size_t)C_ * D_];
static __device__ __align__(16) __half g_bfl[(size_t)C_ * D_];

// ---------------- helpers --------------------------------------------------
__device__ __forceinline__ bool is_split1(const int* sp) {
    int v = *sp;
    return (v == 1) || (v == 0x3F800000);
}

__device__ __forceinline__ uint32_t pack_h2(float a, float b) {
    __half2 h = __floats2half2_rn(a, b);   // low = a, high = b
    return *reinterpret_cast<uint32_t*>(&h);
}
__device__ __forceinline__ uint32_t pack_h2_lo(float a, float b) {
    float ra = a - __half2float(__float2half_rn(a));
    float rb = b - __half2float(__float2half_rn(b));
    __half2 h = __floats2half2_rn(ra, rb);
    return *reinterpret_cast<uint32_t*>(&h);
}

#define MMA16816(C, A, B)                                                    \
    asm volatile(                                                            \
        "mma.sync.aligned.m16n8k16.row.col.f32.f16.f16.f32 "                 \
        "{%0,%1,%2,%3}, {%4,%5,%6,%7}, {%8,%9}, {%0,%1,%2,%3};"              \
        : "+f"((C)[0]), "+f"((C)[1]), "+f"((C)[2]), "+f"((C)[3])             \
        : "r"((A).x), "r"((A).y), "r"((A).z), "r"((A).w),                    \
          "r"((B).x), "r"((B).y))

// ---------------- kernel 1: fused producer ---------------------------------
// Blocks 0..511   : A path. Block = one m-tile (b, 16 consecutive t).
//   Warp w accumulates v_mean for row t=w over n=0..15 in registers (each
//   n-row normalized via warp-shuffle sumsq), stages fp32 in smem, then all
//   512 threads pack complete fp16 A fragments (uint4 per thread, coalesced).
// Blocks 512..543 : B path. Block = 16 c rows (2 n-tiles). Warp w normalizes
//   row c = j*16+w, stages, packs hi+lo B fragments (uint2, coalesced).
__global__ __launch_bounds__(512)
void prep_kernel(const float* __restrict__ v, const float* __restrict__ t,
                 const int* __restrict__ split) {
    __shared__ float sm[16 * D_];   // 32 KB
    int w = threadIdx.x >> 5, lane = threadIdx.x & 31;
    bool s1 = is_split1(split);

    if (blockIdx.x < 512) {
        // ---- A path: v_mean for m-tile ----
        int tile = blockIdx.x;
        int bb = tile >> 4;
        int rt = ((tile & 15) << 4) + w;   // t row for this warp

        float4 a0 = {0,0,0,0}, a1 = {0,0,0,0}, a2 = {0,0,0,0}, a3 = {0,0,0,0};
        const float4* vbase = reinterpret_cast<const float4*>(v);
        size_t roff = (size_t)(bb * NN_) * T_ + rt;

        float4 x0, x1, x2, x3;
        {
            const float4* vp = vbase + roff * (D_ / 4);
            x0 = vp[lane]; x1 = vp[lane + 32]; x2 = vp[lane + 64]; x3 = vp[lane + 96];
        }
        #pragma unroll
        for (int n = 0; n < NN_; n++) {
            float4 y0, y1, y2, y3;
            if (n + 1 < NN_) {
                const float4* vp = vbase + (roff + (size_t)(n + 1) * T_) * (D_ / 4);
                y0 = vp[lane]; y1 = vp[lane + 32]; y2 = vp[lane + 64]; y3 = vp[lane + 96];
            }
            float ss = x0.x*x0.x + x0.y*x0.y + x0.z*x0.z + x0.w*x0.w
                     + x1.x*x1.x + x1.y*x1.y + x1.z*x1.z + x1.w*x1.w
                     + x2.x*x2.x + x2.y*x2.y + x2.z*x2.z + x2.w*x2.w
                     + x3.x*x3.x + x3.y*x3.y + x3.z*x3.z + x3.w*x3.w;
            #pragma unroll
            for (int off = 16; off > 0; off >>= 1)
                ss += __shfl_xor_sync(0xFFFFFFFFu, ss, off);
            float s = (1.0f / 16.0f);
            if (s1) s = (1.0f / 16.0f) / fmaxf(sqrtf(ss), 1e-12f);
            a0.x += x0.x*s; a0.y += x0.y*s; a0.z += x0.z*s; a0.w += x0.w*s;
            a1.x += x1.x*s; a1.y += x1.y*s; a1.z += x1.z*s; a1.w += x1.w*s;
            a2.x += x2.x*s; a2.y += x2.y*s; a2.z += x2.z*s; a2.w += x2.w*s;
            a3.x += x3.x*s; a3.y += x3.y*s; a3.z += x3.z*s; a3.w += x3.w*s;
            x0 = y0; x1 = y1; x2 = y2; x3 = y3;
        }
        float4* smp = reinterpret_cast<float4*>(sm + w * D_);
        smp[lane] = a0; smp[lane + 32] = a1; smp[lane + 64] = a2; smp[lane + 96] = a3;
        __syncthreads();

        // pack A fragments: 1024 frags (32 kt x 32 fl), 2 per thread
        uint4* dst = reinterpret_cast<uint4*>(g_afh) + (size_t)tile * 1024;
        #pragma unroll
        for (int f = threadIdx.x; f < 1024; f += 512) {
            int kt = f >> 5, fl = f & 31;
            int r = fl >> 2;
            int d0 = kt * 16 + (fl & 3) * 2;
            const float* r0 = sm + r * D_ + d0;
            const float* r1 = sm + (r + 8) * D_ + d0;
            uint4 frag;
            frag.x = pack_h2(r0[0], r0[1]);
            frag.y = pack_h2(r1[0], r1[1]);
            frag.z = pack_h2(r0[8], r0[9]);
            frag.w = pack_h2(r1[8], r1[9]);
            dst[f] = frag;
        }
    } else {
        // ---- B path: t_feat normalize, 16 c rows ----
        int j = blockIdx.x - 512;          // 0..31
        int c = j * 16 + w;
        const float4* tp = reinterpret_cast<const float4*>(t) + (size_t)c * (D_ / 4);
        float4 x0 = tp[lane], x1 = tp[lane + 32], x2 = tp[lane + 64], x3 = tp[lane + 96];
        float ss = x0.x*x0.x + x0.y*x0.y + x0.z*x0.z + x0.w*x0.w
                 + x1.x*x1.x + x1.y*x1.y + x1.z*x1.z + x1.w*x1.w
                 + x2.x*x2.x + x2.y*x2.y + x2.z*x2.z + x2.w*x2.w
                 + x3.x*x3.x + x3.y*x3.y + x3.z*x3.z + x3.w*x3.w;
        #pragma unroll
        for (int off = 16; off > 0; off >>= 1)
            ss += __shfl_xor_sync(0xFFFFFFFFu, ss, off);
        float s = 1.0f;
        if (s1) s = 1.0f / fmaxf(sqrtf(ss), 1e-12f);

        float4* smp = reinterpret_cast<float4*>(sm + w * D_);
        smp[lane]      = make_float4(x0.x*s, x0.y*s, x0.z*s, x0.w*s);
        smp[lane + 32] = make_float4(x1.x*s, x1.y*s, x1.z*s, x1.w*s);
        smp[lane + 64] = make_float4(x2.x*s, x2.y*s, x2.z*s, x2.w*s);
        smp[lane + 96] = make_float4(x3.x*s, x3.y*s, x3.z*s, x3.w*s);
        __syncthreads();

        // pack B fragments: 2 nt x 32 kt x 32 fl = 2048 frags, hi+lo, 4 each
        uint2* dh = reinterpret_cast<uint2*>(g_bfh);
        uint2* dl = reinterpret_cast<uint2*>(g_bfl);
        #pragma unroll
        for (int f = threadIdx.x; f < 2048; f += 512) {
            int ntl = f >> 10, kt = (f >> 5) & 31, fl = f & 31;
            int nl = ntl * 8 + (fl >> 2);       // c_local 0..15
            int k0 = kt * 16 + (fl & 3) * 2;
            const float* r0 = sm + nl * D_ + k0;
            uint2 fh, flo;
            fh.x  = pack_h2(r0[0], r0[1]);
            fh.y  = pack_h2(r0[8], r0[9]);
            flo.x = pack_h2_lo(r0[0], r0[1]);
            flo.y = pack_h2_lo(r0[8], r0[9]);
            size_t idx = (((size_t)(j * 2 + ntl) * 32 + kt) << 5) + fl;
            dh[idx] = fh;
            dl[idx] = flo;
        }
    }
}

// ---------------- kernel 2: fp16 2-term mma.sync GEMM ----------------------
// D[m, c] = sum_d A[m,d]*B[c,d]; out[b][c][t] = D/tau.
// 2 MMAs per (tile, k16): Ahi*Bhi + Ahi*Blo (A rounding error ~1.4e-4 rel,
// B fully corrected). CTA 128x128, 16 warps, warp tile 32x32.
__global__ __launch_bounds__(512)
void gemm_mma_kernel(float* __restrict__ out) {
    int tid = threadIdx.x;
    int w = tid >> 5, lane = tid & 31;
    int wm = w >> 2, wn = w & 3;
    int m0 = blockIdx.y * 128 + wm * 32;
    int n0 = blockIdx.x * 128 + wn * 32;

    const uint4* pA  = reinterpret_cast<const uint4*>(g_afh) + (size_t)(m0 >> 4) * (KT16 * 32) + lane;
    const uint2* pBh = reinterpret_cast<const uint2*>(g_bfh) + (size_t)(n0 >> 3) * (KT16 * 32) + lane;
    const uint2* pBl = reinterpret_cast<const uint2*>(g_bfl) + (size_t)(n0 >> 3) * (KT16 * 32) + lane;

    float acc[2][4][4];
    #pragma unroll
    for (int mi = 0; mi < 2; mi++)
        #pragma unroll
        for (int ni = 0; ni < 4; ni++)
            #pragma unroll
            for (int j = 0; j < 4; j++) acc[mi][ni][j] = 0.0f;

    uint4 A[2][2];
    uint2 Bh[2][4], Bl[2][4];

    #pragma unroll
    for (int mi = 0; mi < 2; mi++) A[0][mi] = pA[mi * (KT16 * 32)];
    #pragma unroll
    for (int ni = 0; ni < 4; ni++) {
        Bh[0][ni] = pBh[ni * (KT16 * 32)];
        Bl[0][ni] = pBl[ni * (KT16 * 32)];
    }

    #pragma unroll
    for (int kt = 0; kt < KT16; kt++) {
        int cur = kt & 1, nxt = cur ^ 1;
        if (kt + 1 < KT16) {
            int ko = (kt + 1) * 32;
            #pragma unroll
            for (int mi = 0; mi < 2; mi++) A[nxt][mi] = pA[mi * (KT16 * 32) + ko];
            #pragma unroll
            for (int ni = 0; ni < 4; ni++) {
                Bh[nxt][ni] = pBh[ni * (KT16 * 32) + ko];
                Bl[nxt][ni] = pBl[ni * (KT16 * 32) + ko];
            }
        }
        #pragma unroll
        for (int mi = 0; mi < 2; mi++)
            #pragma unroll
            for (int ni = 0; ni < 4; ni++) {
                MMA16816(acc[mi][ni], A[cur][mi], Bh[cur][ni]);
                MMA16816(acc[mi][ni], A[cur][mi], Bl[cur][ni]);
            }
    }

    // epilogue: out[b][c][t] (t contiguous, stride 256 per c)
    int b = m0 >> 8;
    int t = (m0 & 255) + (lane >> 2);
    const float s = 1.0f / 0.07f;   // 1/tau (both splits)
    #pragma unroll
    for (int mi = 0; mi < 2; mi++) {
        #pragma unroll
        for (int ni = 0; ni < 4; ni++) {
            int c = n0 + ni * 8 + (lane & 3) * 2;
            float* p = out + (((size_t)b * C_ + c) << 8) + t + mi * 16;
            p[0]   = acc[mi][ni][0] * s;
            p[256] = acc[mi][ni][1] * s;
            p[8]   = acc[mi][ni][2] * s;
            p[264] = acc[mi][ni][3] * s;
        }
    }
}

// ---------------- launch ---------------------------------------------------
extern "C" void kernel_launch(void* const* d_in, const int* in_sizes, int n_in,
                              void* d_out, int out_size) {
    const float* v = nullptr;
    const float* t = nullptr;
    const int* split = nullptr;
    for (int i = 0; i < n_in; i++) {
        if (in_sizes[i] == B_ * NN_ * T_ * D_) v = (const float*)d_in[i];
        else if (in_sizes[i] == C_ * D_)       t = (const float*)d_in[i];
        else                                    split = (const int*)d_in[i];
    }
    float* out = (float*)d_out;

    prep_kernel<<<544, 512>>>(v, t, split);          // 512 A-tiles + 32 B-blocks
    dim3 grid(C_ / 128, M_ / 128);                   // (4, 64) = 256 CTAs
    gemm_mma_kernel<<<grid, 512>>>(out);
}